// round 1
// baseline (speedup 1.0000x reference)
#include <cuda_runtime.h>
#include <math.h>

#define SEQ_T 256
#define NB    64
#define DIM   512
#define TBM   (SEQ_T * NB * DIM)   /* 8388608 */

// Scratch (static device allocations are permitted; no runtime alloc).
__device__ float g_iou[SEQ_T * NB * 4 * DIM];   // [T*B, 2048]  (+ b_ioux + b_ious)
__device__ float g_ctx[SEQ_T * NB * DIM];       // [T*B, 512]   (+ b_fx)
__device__ float g_wcs[SEQ_T * NB * DIM];       // [T*B, 512]   tanh(emb@W_wc.T + b_wc)
__device__ unsigned g_cnt;                      // grid-barrier counter

__global__ void init_kernel() { g_cnt = 0u; }

// ---------------------------------------------------------------------------
// Generic fp32 SGEMM: C[Mrows x N] = A[Mrows x K] * B[N x K]^T + bias (+tanh)
// K may be a virtual concat of two 512-wide sources (A0/B0 for k<512, A1/B1 after).
// BM=BN=128, BK=16, 256 threads, 8x8 register tile per thread.
// ---------------------------------------------------------------------------
__global__ void __launch_bounds__(256) gemm_kernel(
    int mode,
    const float* __restrict__ A0, const float* __restrict__ A1,
    const float* __restrict__ B0, const float* __restrict__ B1,
    const float* __restrict__ bias0, const float* __restrict__ bias1,
    int N, int K)
{
    float* C = (mode == 0) ? g_iou : (mode == 1) ? g_ctx : g_wcs;

    __shared__ float As[16 * 132];
    __shared__ float Bs[16 * 132];

    const int tid = threadIdx.x;
    const int bm  = blockIdx.y * 128;
    const int bn  = blockIdx.x * 128;
    const int tx  = tid & 15;
    const int ty  = tid >> 4;

    float acc[8][8];
    #pragma unroll
    for (int i = 0; i < 8; i++)
        #pragma unroll
        for (int j = 0; j < 8; j++) acc[i][j] = 0.f;

    for (int k0 = 0; k0 < K; k0 += 16) {
        const float* Asrc; const float* Bsrc; int ko;
        if (k0 < 512) { Asrc = A0; Bsrc = B0; ko = k0; }
        else          { Asrc = A1; Bsrc = B1; ko = k0 - 512; }

        #pragma unroll
        for (int i = 0; i < 2; i++) {
            int l  = tid + i * 256;
            int r  = l >> 2;
            int c4 = (l & 3) * 4;
            float4 av = *reinterpret_cast<const float4*>(Asrc + (bm + r) * 512 + ko + c4);
            As[(c4 + 0) * 132 + r] = av.x;
            As[(c4 + 1) * 132 + r] = av.y;
            As[(c4 + 2) * 132 + r] = av.z;
            As[(c4 + 3) * 132 + r] = av.w;
            float4 bv = *reinterpret_cast<const float4*>(Bsrc + (bn + r) * 512 + ko + c4);
            Bs[(c4 + 0) * 132 + r] = bv.x;
            Bs[(c4 + 1) * 132 + r] = bv.y;
            Bs[(c4 + 2) * 132 + r] = bv.z;
            Bs[(c4 + 3) * 132 + r] = bv.w;
        }
        __syncthreads();

        #pragma unroll
        for (int kk = 0; kk < 16; kk++) {
            float a8[8], b8[8];
            *reinterpret_cast<float4*>(a8)     = *reinterpret_cast<const float4*>(&As[kk * 132 + ty * 8]);
            *reinterpret_cast<float4*>(a8 + 4) = *reinterpret_cast<const float4*>(&As[kk * 132 + ty * 8 + 4]);
            *reinterpret_cast<float4*>(b8)     = *reinterpret_cast<const float4*>(&Bs[kk * 132 + tx * 8]);
            *reinterpret_cast<float4*>(b8 + 4) = *reinterpret_cast<const float4*>(&Bs[kk * 132 + tx * 8 + 4]);
            #pragma unroll
            for (int i = 0; i < 8; i++)
                #pragma unroll
                for (int j = 0; j < 8; j++)
                    acc[i][j] += a8[i] * b8[j];
        }
        __syncthreads();
    }

    const int col0 = bn + tx * 8;
    float bias[8];
    #pragma unroll
    for (int j = 0; j < 8; j++) {
        float v = bias0[col0 + j];
        if (bias1) v += bias1[col0 + j];
        bias[j] = v;
    }
    #pragma unroll
    for (int i = 0; i < 8; i++) {
        int row = bm + ty * 8 + i;
        float out8[8];
        #pragma unroll
        for (int j = 0; j < 8; j++) {
            float v = acc[i][j] + bias[j];
            if (mode == 2) v = tanhf(v);
            out8[j] = v;
        }
        float* Cp = C + (size_t)row * N + col0;
        *reinterpret_cast<float4*>(Cp)     = *reinterpret_cast<float4*>(out8);
        *reinterpret_cast<float4*>(Cp + 4) = *reinterpret_cast<float4*>(out8 + 4);
    }
}

// ---------------------------------------------------------------------------
// Persistent recurrence kernel. grid = 128 blocks (<=148 SMs, all co-resident),
// 256 threads. Thread owns one (b, m) cell: 5 length-512 dot products per step
// (gates f/i/o/o_c via W_iouh rows, c_telta via W_fh row). Weights via __ldg
// (L1-resident: 40KB/block, persists across the whole t-loop). h_{t-1} read
// via __ldcg (L2 only -> coherent across blocks). Hand-rolled grid barrier.
// ---------------------------------------------------------------------------
__device__ __forceinline__ float sigmoidf_(float x) { return 1.f / (1.f + expf(-x)); }

__global__ void __launch_bounds__(256) scan_kernel(
    const float* __restrict__ W_iouh, const float* __restrict__ b_iouh,
    const float* __restrict__ W_fh,   const float* __restrict__ b_fh,
    const float* __restrict__ c0,     const float* __restrict__ h0,
    float* __restrict__ out)
{
    const int tid = threadIdx.x;
    const int mi  = tid & 3;
    const int b   = tid >> 2;
    const int m   = blockIdx.x * 4 + mi;

    const float4* wf  = reinterpret_cast<const float4*>(W_iouh + (0 * 512 + m) * 512);
    const float4* wi  = reinterpret_cast<const float4*>(W_iouh + (1 * 512 + m) * 512);
    const float4* wo  = reinterpret_cast<const float4*>(W_iouh + (2 * 512 + m) * 512);
    const float4* woc = reinterpret_cast<const float4*>(W_iouh + (3 * 512 + m) * 512);
    const float4* wfh = reinterpret_cast<const float4*>(W_fh + m * 512);

    const float bif  = b_iouh[m];
    const float bii  = b_iouh[512 + m];
    const float bio  = b_iouh[1024 + m];
    const float bioc = b_iouh[1536 + m];
    const float bfh  = b_fh[m];

    float c     = c0[b * 512 + m];
    float h_val = 0.f;

    for (int t = 0; t < SEQ_T; t++) {
        const float* hbase = (t == 0) ? h0 : (out + (size_t)(t - 1) * (NB * DIM));
        const float4* hp = reinterpret_cast<const float4*>(hbase) + b * 128;

        float a0 = 0.f, a1 = 0.f, a2 = 0.f, a3 = 0.f, a4 = 0.f;
        #pragma unroll 8
        for (int k = 0; k < 128; k++) {
            float4 h4 = __ldcg(hp + k);
            float4 w;
            w = __ldg(wf  + k); a0 += h4.x * w.x + h4.y * w.y + h4.z * w.z + h4.w * w.w;
            w = __ldg(wi  + k); a1 += h4.x * w.x + h4.y * w.y + h4.z * w.z + h4.w * w.w;
            w = __ldg(wo  + k); a2 += h4.x * w.x + h4.y * w.y + h4.z * w.z + h4.w * w.w;
            w = __ldg(woc + k); a3 += h4.x * w.x + h4.y * w.y + h4.z * w.z + h4.w * w.w;
            w = __ldg(wfh + k); a4 += h4.x * w.x + h4.y * w.y + h4.z * w.z + h4.w * w.w;
        }

        const int row = t * NB + b;
        const float* giou = g_iou + (size_t)row * 2048;
        float fg  = sigmoidf_(a0 + giou[m]         + bif);
        float ig  = sigmoidf_(a1 + giou[512 + m]   + bii);
        float og  = sigmoidf_(a2 + giou[1024 + m]  + bio);
        float ocg = sigmoidf_(a3 + giou[1536 + m]  + bioc);
        float ct  = tanhf(a4 + g_ctx[(size_t)row * 512 + m] + bfh);

        c     = ig * ct + fg * c;
        h_val = og * tanhf(c) + ocg * g_wcs[(size_t)row * 512 + m];
        out[(size_t)t * (NB * DIM) + b * 512 + m] = h_val;

        // ---- grid barrier: release (fence by every thread) -> arrive -> spin -> acquire
        __threadfence();
        __syncthreads();
        if (tid == 0) {
            atomicAdd(&g_cnt, 1u);
            const unsigned target = (unsigned)gridDim.x * (unsigned)(t + 1);
            while (*reinterpret_cast<volatile unsigned*>(&g_cnt) < target) { }
            __threadfence();
        }
        __syncthreads();
    }

    // tails: c_fin then h_fin
    out[TBM + b * 512 + m]            = c;
    out[TBM + NB * DIM + b * 512 + m] = h_val;
}

// ---------------------------------------------------------------------------
extern "C" void kernel_launch(void* const* d_in, const int* in_sizes, int n_in,
                              void* d_out, int out_size)
{
    const float* inputs = (const float*)d_in[0];
    const float* emb_s  = (const float*)d_in[1];
    const float* c0     = (const float*)d_in[2];
    const float* h0     = (const float*)d_in[3];
    const float* W_ioux = (const float*)d_in[4];
    const float* b_ioux = (const float*)d_in[5];
    const float* W_iouh = (const float*)d_in[6];
    const float* b_iouh = (const float*)d_in[7];
    const float* W_ious = (const float*)d_in[8];
    const float* b_ious = (const float*)d_in[9];
    const float* W_fx   = (const float*)d_in[10];
    const float* b_fx   = (const float*)d_in[11];
    const float* W_fh   = (const float*)d_in[12];
    const float* b_fh   = (const float*)d_in[13];
    const float* W_wc   = (const float*)d_in[14];
    const float* b_wc   = (const float*)d_in[15];
    float* out = (float*)d_out;

    init_kernel<<<1, 1>>>();
    // iou_x: [16384 x 2048], virtual K=1024 ([inputs|emb] x [W_ioux;W_ious])
    gemm_kernel<<<dim3(16, 128), 256>>>(0, inputs, emb_s, W_ioux, W_ious,
                                        b_ioux, b_ious, 2048, 1024);
    // ctelta_x: [16384 x 512]
    gemm_kernel<<<dim3(4, 128), 256>>>(1, inputs, nullptr, W_fx, nullptr,
                                       b_fx, nullptr, 512, 512);
    // wc_s = tanh(...): [16384 x 512]
    gemm_kernel<<<dim3(4, 128), 256>>>(2, emb_s, nullptr, W_wc, nullptr,
                                       b_wc, nullptr, 512, 512);
    // sequential scan (persistent, grid-barrier per step)
    scan_kernel<<<128, 256>>>(W_iouh, b_iouh, W_fh, b_fh, c0, h0, out);
}

// round 2
// speedup vs baseline: 2.0379x; 2.0379x over previous
#include <cuda_runtime.h>
#include <math.h>

#define SEQ_T 256
#define NB    64
#define DIM   512
#define TBM   (SEQ_T * NB * DIM)   /* 8388608 */

// ---------------- scratch (static device memory; no runtime alloc) ----------
__device__ float g_iouT[(size_t)SEQ_T * 4 * DIM * NB];  // [t][gate][m][b]
__device__ float g_ctxT[(size_t)SEQ_T * DIM * NB];      // [t][m][b]
__device__ float g_wcsT[(size_t)SEQ_T * DIM * NB];      // [t][m][b]  (tanh applied)
__device__ float g_hT  [(size_t)SEQ_T * DIM * NB];      // [t][m][b]  h history (transposed)
__device__ float g_h0T [DIM * NB];                      // [m][b]
__device__ float g_cT  [DIM * NB];                      // [m][b]
__device__ unsigned g_cnt;

// ---------------------------------------------------------------------------
__global__ void init_kernel(const float* __restrict__ h0) {
    int b = blockIdx.x;          // 64 blocks
    int m = threadIdx.x;         // 512 threads
    g_h0T[m * NB + b] = h0[b * DIM + m];
    if (b == 0 && m == 0) g_cnt = 0u;
}

// ---------------------------------------------------------------------------
// fp32 SGEMM: C[Mrows x N] = A * B^T + bias (+tanh), transposed stores into
// the scan-friendly layouts. K may be virtual concat of two 512-wide sources.
// BM=BN=128, BK=16, 256 threads, 8x8 register tile.
// ---------------------------------------------------------------------------
__global__ void __launch_bounds__(256) gemm_kernel(
    int mode,
    const float* __restrict__ A0, const float* __restrict__ A1,
    const float* __restrict__ B0, const float* __restrict__ B1,
    const float* __restrict__ bias0, const float* __restrict__ bias1,
    int N, int K)
{
    __shared__ float As[16 * 132];
    __shared__ float Bs[16 * 132];

    const int tid = threadIdx.x;
    const int bm  = blockIdx.y * 128;
    const int bn  = blockIdx.x * 128;
    const int tx  = tid & 15;
    const int ty  = tid >> 4;

    float acc[8][8];
    #pragma unroll
    for (int i = 0; i < 8; i++)
        #pragma unroll
        for (int j = 0; j < 8; j++) acc[i][j] = 0.f;

    for (int k0 = 0; k0 < K; k0 += 16) {
        const float* Asrc; const float* Bsrc; int ko;
        if (k0 < 512) { Asrc = A0; Bsrc = B0; ko = k0; }
        else          { Asrc = A1; Bsrc = B1; ko = k0 - 512; }

        #pragma unroll
        for (int i = 0; i < 2; i++) {
            int l  = tid + i * 256;
            int r  = l >> 2;
            int c4 = (l & 3) * 4;
            float4 av = *reinterpret_cast<const float4*>(Asrc + (size_t)(bm + r) * 512 + ko + c4);
            As[(c4 + 0) * 132 + r] = av.x;
            As[(c4 + 1) * 132 + r] = av.y;
            As[(c4 + 2) * 132 + r] = av.z;
            As[(c4 + 3) * 132 + r] = av.w;
            float4 bv = *reinterpret_cast<const float4*>(Bsrc + (size_t)(bn + r) * 512 + ko + c4);
            Bs[(c4 + 0) * 132 + r] = bv.x;
            Bs[(c4 + 1) * 132 + r] = bv.y;
            Bs[(c4 + 2) * 132 + r] = bv.z;
            Bs[(c4 + 3) * 132 + r] = bv.w;
        }
        __syncthreads();

        #pragma unroll
        for (int kk = 0; kk < 16; kk++) {
            float a8[8], b8[8];
            *reinterpret_cast<float4*>(a8)     = *reinterpret_cast<const float4*>(&As[kk * 132 + ty * 8]);
            *reinterpret_cast<float4*>(a8 + 4) = *reinterpret_cast<const float4*>(&As[kk * 132 + ty * 8 + 4]);
            *reinterpret_cast<float4*>(b8)     = *reinterpret_cast<const float4*>(&Bs[kk * 132 + tx * 8]);
            *reinterpret_cast<float4*>(b8 + 4) = *reinterpret_cast<const float4*>(&Bs[kk * 132 + tx * 8 + 4]);
            #pragma unroll
            for (int i = 0; i < 8; i++)
                #pragma unroll
                for (int j = 0; j < 8; j++)
                    acc[i][j] += a8[i] * b8[j];
        }
        __syncthreads();
    }

    const int col0 = bn + tx * 8;
    float bias[8];
    #pragma unroll
    for (int j = 0; j < 8; j++) {
        float v = bias0[col0 + j];
        if (bias1) v += bias1[col0 + j];
        bias[j] = v;
    }

    #pragma unroll
    for (int i = 0; i < 8; i++) {
        int row = bm + ty * 8 + i;
        int t   = row >> 6;
        int b   = row & 63;
        #pragma unroll
        for (int j = 0; j < 8; j++) {
            float v = acc[i][j] + bias[j];
            int col = col0 + j;
            if (mode == 0) {
                int g  = col >> 9;
                int mc = col & 511;
                g_iouT[(((size_t)t * 4 + g) * 512 + mc) * 64 + b] = v;
            } else if (mode == 1) {
                g_ctxT[(size_t)t * (512 * 64) + (size_t)col * 64 + b] = v;
            } else {
                g_wcsT[(size_t)t * (512 * 64) + (size_t)col * 64 + b] = tanhf(v);
            }
        }
    }
}

// ---------------------------------------------------------------------------
// Persistent weight-stationary scan. 128 blocks (all co-resident), 256 threads.
// Block owns 4 m-columns; weights (5 gates x 4 m x 512 k = 40KB) live in smem.
// warp = m_local(4) x bhalf(2); lane = kc(4, bits 3-4) x bq(8, bits 0-2).
// Thread accumulates 4b x 5gates partials over its 128-k slice; shfl-reduce
// over kc; lane kc picks b = 32*bhalf + 4*bq + kc for the gate math (c stays
// in a register across all 256 steps).
// ---------------------------------------------------------------------------
__device__ __forceinline__ float sigmoidf_(float x) { return 1.f / (1.f + expf(-x)); }

__global__ void __launch_bounds__(256) scan_kernel(
    const float* __restrict__ W_iouh, const float* __restrict__ b_iouh,
    const float* __restrict__ W_fh,   const float* __restrict__ b_fh,
    const float* __restrict__ c0)
{
    // W4: [m_l][kc][i][g0..3] with per-kc skew of 1 float4 -> kc stride 516
    // W1: [m_l][kc][i]        with per-kc skew of 4 floats -> kc stride 132
    __shared__ float Wsm4[4 * 2064];   // 8256 floats
    __shared__ float Wsm1[4 * 528];    // 2112 floats  (total 41.5 KB)

    const int tid   = threadIdx.x;
    const int warp  = tid >> 5;
    const int lane  = tid & 31;
    const int m_l   = warp >> 1;
    const int bhalf = warp & 1;
    const int kc    = (lane >> 3) & 3;
    const int bq    = lane & 7;
    const int m     = blockIdx.x * 4 + m_l;
    const int b_own = bhalf * 32 + bq * 4 + kc;

    // ---- load weights into smem (once) ----
    for (int idx = tid; idx < 4 * 4 * 128 * 4; idx += 256) {
        int ml = idx >> 11;
        int r  = idx & 2047;
        int c  = r >> 9;            // kc
        int r2 = r & 511;
        int i  = r2 >> 2;
        int g  = r2 & 3;
        int mg = blockIdx.x * 4 + ml;
        Wsm4[ml * 2064 + c * 516 + i * 4 + g] =
            W_iouh[((size_t)g * 512 + mg) * 512 + c * 128 + i];
    }
    for (int idx = tid; idx < 4 * 4 * 128; idx += 256) {
        int ml = idx >> 9;
        int r  = idx & 511;
        int c  = r >> 7;
        int i  = r & 127;
        int mg = blockIdx.x * 4 + ml;
        Wsm1[ml * 528 + c * 132 + i] = W_fh[(size_t)mg * 512 + c * 128 + i];
    }
    __syncthreads();

    const float bf  = b_iouh[m];
    const float bi  = b_iouh[512 + m];
    const float bo  = b_iouh[1024 + m];
    const float boc = b_iouh[1536 + m];
    const float bfh = b_fh[m];

    float c_reg = c0[(size_t)b_own * 512 + m];

    const float4* w4p = reinterpret_cast<const float4*>(Wsm4 + m_l * 2064 + kc * 516);
    const float*  w1p = Wsm1 + m_l * 528 + kc * 132;
    const int hoff = kc * 2048 + bhalf * 8 + bq;   // float4 index within a step slice

    for (int t = 0; t < SEQ_T; t++) {
        const float* hb = (t == 0) ? g_h0T : (g_hT + (size_t)(t - 1) * (DIM * NB));
        const float4* hp = reinterpret_cast<const float4*>(hb) + hoff;

        float a[20];
        #pragma unroll
        for (int q = 0; q < 20; q++) a[q] = 0.f;

        #pragma unroll 8
        for (int i = 0; i < 128; i++) {
            float4 h4 = __ldg(hp + i * 16);
            float4 w4 = w4p[i];
            float  w1 = w1p[i];
            #pragma unroll
            for (int j = 0; j < 4; j++) {
                float hj = (j == 0) ? h4.x : (j == 1) ? h4.y : (j == 2) ? h4.z : h4.w;
                a[j * 5 + 0] += hj * w4.x;
                a[j * 5 + 1] += hj * w4.y;
                a[j * 5 + 2] += hj * w4.z;
                a[j * 5 + 3] += hj * w4.w;
                a[j * 5 + 4] += hj * w1;
            }
        }

        // reduce over kc (lane bits 3,4)
        #pragma unroll
        for (int q = 0; q < 20; q++) {
            a[q] += __shfl_xor_sync(0xffffffffu, a[q], 8);
            a[q] += __shfl_xor_sync(0xffffffffu, a[q], 16);
        }

        // lane handles b_own (j = kc row of its quad)
        const size_t ib = (((size_t)t * 4) * 512 + m) * 64 + b_own;
        const size_t sb = (size_t)t * (512 * 64) + (size_t)m * 64 + b_own;
        float af  = g_iouT[ib];
        float ai  = g_iouT[ib + 1 * 512 * 64];
        float ao  = g_iouT[ib + 2 * 512 * 64];
        float aoc = g_iouT[ib + 3 * 512 * 64];
        float act = g_ctxT[sb];
        float aw  = g_wcsT[sb];

        float fg  = sigmoidf_(a[kc * 5 + 0] + af  + bf);
        float ig  = sigmoidf_(a[kc * 5 + 1] + ai  + bi);
        float og  = sigmoidf_(a[kc * 5 + 2] + ao  + bo);
        float ocg = sigmoidf_(a[kc * 5 + 3] + aoc + boc);
        float ct  = tanhf    (a[kc * 5 + 4] + act + bfh);

        c_reg = ig * ct + fg * c_reg;
        float hv = og * tanhf(c_reg) + ocg * aw;

        g_hT[sb] = hv;

        // ---- grid barrier ----
        __threadfence();
        __syncthreads();
        if (tid == 0) {
            atomicAdd(&g_cnt, 1u);
            const unsigned target = (unsigned)gridDim.x * (unsigned)(t + 1);
            while (*reinterpret_cast<volatile unsigned*>(&g_cnt) < target) { }
            __threadfence();
        }
        __syncthreads();
    }

    g_cT[(size_t)m * 64 + b_own] = c_reg;
}

// ---------------------------------------------------------------------------
// transpose g_hT [t][m][b] -> out [t][b][m]
// ---------------------------------------------------------------------------
__global__ void __launch_bounds__(256) transpose_kernel(float* __restrict__ out)
{
    __shared__ float tile[32][33];
    const int tx = threadIdx.x;       // 0..31
    const int ty = threadIdx.y;       // 0..7
    const int m0 = blockIdx.x * 32;
    const int b0 = blockIdx.y * 32;
    const int t  = blockIdx.z;

    const float* src = g_hT + (size_t)t * (512 * 64);
    #pragma unroll
    for (int k = 0; k < 4; k++)
        tile[ty + 8 * k][tx] = src[(size_t)(m0 + ty + 8 * k) * 64 + b0 + tx];
    __syncthreads();
    float* dst = out + (size_t)t * (64 * 512);
    #pragma unroll
    for (int k = 0; k < 4; k++)
        dst[(size_t)(b0 + ty + 8 * k) * 512 + m0 + tx] = tile[tx][ty + 8 * k];
}

__global__ void tail_kernel(float* __restrict__ out)
{
    int b = blockIdx.x;      // 64
    int m = threadIdx.x;     // 512
    out[TBM + (size_t)b * 512 + m]             = g_cT[(size_t)m * 64 + b];
    out[TBM + NB * DIM + (size_t)b * 512 + m]  = g_hT[(size_t)255 * (512 * 64) + (size_t)m * 64 + b];
}

// ---------------------------------------------------------------------------
extern "C" void kernel_launch(void* const* d_in, const int* in_sizes, int n_in,
                              void* d_out, int out_size)
{
    const float* inputs = (const float*)d_in[0];
    const float* emb_s  = (const float*)d_in[1];
    const float* c0     = (const float*)d_in[2];
    const float* h0     = (const float*)d_in[3];
    const float* W_ioux = (const float*)d_in[4];
    const float* b_ioux = (const float*)d_in[5];
    const float* W_iouh = (const float*)d_in[6];
    const float* b_iouh = (const float*)d_in[7];
    const float* W_ious = (const float*)d_in[8];
    const float* b_ious = (const float*)d_in[9];
    const float* W_fx   = (const float*)d_in[10];
    const float* b_fx   = (const float*)d_in[11];
    const float* W_fh   = (const float*)d_in[12];
    const float* b_fh   = (const float*)d_in[13];
    const float* W_wc   = (const float*)d_in[14];
    const float* b_wc   = (const float*)d_in[15];
    float* out = (float*)d_out;

    init_kernel<<<64, 512>>>(h0);
    // iou_x: [16384 x 2048], virtual K=1024 ([inputs|emb] x [W_ioux;W_ious])
    gemm_kernel<<<dim3(16, 128), 256>>>(0, inputs, emb_s, W_ioux, W_ious,
                                        b_ioux, b_ious, 2048, 1024);
    // ctelta_x: [16384 x 512]
    gemm_kernel<<<dim3(4, 128), 256>>>(1, inputs, nullptr, W_fx, nullptr,
                                       b_fx, nullptr, 512, 512);
    // wc_s = tanh(...): [16384 x 512]
    gemm_kernel<<<dim3(4, 128), 256>>>(2, emb_s, nullptr, W_wc, nullptr,
                                       b_wc, nullptr, 512, 512);
    // sequential scan (persistent, grid barrier per step)
    scan_kernel<<<128, 256>>>(W_iouh, b_iouh, W_fh, b_fh, c0);
    // produce out[t][b][m] + tails
    transpose_kernel<<<dim3(16, 2, 256), dim3(32, 8)>>>(out);
    tail_kernel<<<64, 512>>>(out);
}

// round 3
// speedup vs baseline: 2.1861x; 1.0727x over previous
#include <cuda_runtime.h>
#include <math.h>

#define SEQ_T 256
#define NB    64
#define DIM   512
#define TBM   (SEQ_T * NB * DIM)   /* 8388608 */

// ---------------- scratch (static device memory; no runtime alloc) ----------
__device__ float g_iouT[(size_t)SEQ_T * 4 * DIM * NB];  // [t][gate][m][b]
__device__ float g_ctxT[(size_t)SEQ_T * DIM * NB];      // [t][m][b]
__device__ float g_wcsT[(size_t)SEQ_T * DIM * NB];      // [t][m][b]  (tanh applied)
__device__ float g_hT  [(size_t)SEQ_T * DIM * NB];      // [t][m][b]  h history (transposed)
__device__ float g_h0T [DIM * NB];                      // [m][b]
__device__ float g_cT  [DIM * NB];                      // [m][b]
__device__ unsigned g_cnt;

typedef unsigned long long ull;

__device__ __forceinline__ void ffma2(ull& d, ull a, ull b) {
    asm("fma.rn.f32x2 %0, %1, %2, %0;" : "+l"(d) : "l"(a), "l"(b));
}
__device__ __forceinline__ ull packdup(float a) {
    ull r; asm("mov.b64 %0, {%1, %1};" : "=l"(r) : "f"(a)); return r;
}
__device__ __forceinline__ float tanh_fast(float x) {
    float y; asm("tanh.approx.f32 %0, %1;" : "=f"(y) : "f"(x)); return y;
}
__device__ __forceinline__ float sigmoid_fast(float x) {
    return fmaf(0.5f, tanh_fast(0.5f * x), 0.5f);
}

// ---------------------------------------------------------------------------
__global__ void init_kernel(const float* __restrict__ h0) {
    int b = blockIdx.x;          // 64 blocks
    int m = threadIdx.x;         // 512 threads
    g_h0T[m * NB + b] = h0[b * DIM + m];
    if (b == 0 && m == 0) g_cnt = 0u;
}

// ---------------------------------------------------------------------------
// fp32 SGEMM with packed FFMA2: C = A * B^T + bias (+tanh), transposed stores.
// BM=BN=128, BK=16, 256 threads, 8x8 register tile (as 8x4 f32x2 pairs).
// ---------------------------------------------------------------------------
__global__ void __launch_bounds__(256) gemm_kernel(
    int mode,
    const float* __restrict__ A0, const float* __restrict__ A1,
    const float* __restrict__ B0, const float* __restrict__ B1,
    const float* __restrict__ bias0, const float* __restrict__ bias1,
    int N, int K)
{
    __shared__ float As[16 * 132];
    __shared__ float Bs[16 * 132];

    const int tid = threadIdx.x;
    const int bm  = blockIdx.y * 128;
    const int bn  = blockIdx.x * 128;
    const int tx  = tid & 15;
    const int ty  = tid >> 4;

    ull accP[8][4];
    #pragma unroll
    for (int i = 0; i < 8; i++)
        #pragma unroll
        for (int j = 0; j < 4; j++) accP[i][j] = 0ull;

    for (int k0 = 0; k0 < K; k0 += 16) {
        const float* Asrc; const float* Bsrc; int ko;
        if (k0 < 512) { Asrc = A0; Bsrc = B0; ko = k0; }
        else          { Asrc = A1; Bsrc = B1; ko = k0 - 512; }

        #pragma unroll
        for (int i = 0; i < 2; i++) {
            int l  = tid + i * 256;
            int r  = l >> 2;
            int c4 = (l & 3) * 4;
            float4 av = *reinterpret_cast<const float4*>(Asrc + (size_t)(bm + r) * 512 + ko + c4);
            As[(c4 + 0) * 132 + r] = av.x;
            As[(c4 + 1) * 132 + r] = av.y;
            As[(c4 + 2) * 132 + r] = av.z;
            As[(c4 + 3) * 132 + r] = av.w;
            float4 bv = *reinterpret_cast<const float4*>(Bsrc + (size_t)(bn + r) * 512 + ko + c4);
            Bs[(c4 + 0) * 132 + r] = bv.x;
            Bs[(c4 + 1) * 132 + r] = bv.y;
            Bs[(c4 + 2) * 132 + r] = bv.z;
            Bs[(c4 + 3) * 132 + r] = bv.w;
        }
        __syncthreads();

        #pragma unroll
        for (int kk = 0; kk < 16; kk++) {
            float a8[8];
            float4 b0 = *reinterpret_cast<const float4*>(&Bs[kk * 132 + tx * 8]);
            float4 b1 = *reinterpret_cast<const float4*>(&Bs[kk * 132 + tx * 8 + 4]);
            *reinterpret_cast<float4*>(a8)     = *reinterpret_cast<const float4*>(&As[kk * 132 + ty * 8]);
            *reinterpret_cast<float4*>(a8 + 4) = *reinterpret_cast<const float4*>(&As[kk * 132 + ty * 8 + 4]);
            ull bp[4];
            bp[0] = reinterpret_cast<const ulonglong2*>(&b0)->x;
            bp[1] = reinterpret_cast<const ulonglong2*>(&b0)->y;
            bp[2] = reinterpret_cast<const ulonglong2*>(&b1)->x;
            bp[3] = reinterpret_cast<const ulonglong2*>(&b1)->y;
            #pragma unroll
            for (int i = 0; i < 8; i++) {
                ull ad = packdup(a8[i]);
                #pragma unroll
                for (int j = 0; j < 4; j++)
                    ffma2(accP[i][j], ad, bp[j]);
            }
        }
        __syncthreads();
    }

    const int col0 = bn + tx * 8;
    float bias[8];
    #pragma unroll
    for (int j = 0; j < 8; j++) {
        float v = bias0[col0 + j];
        if (bias1) v += bias1[col0 + j];
        bias[j] = v;
    }

    #pragma unroll
    for (int i = 0; i < 8; i++) {
        int row = bm + ty * 8 + i;
        int t   = row >> 6;
        int b   = row & 63;
        #pragma unroll
        for (int j = 0; j < 8; j++) {
            float2 pr = *reinterpret_cast<float2*>(&accP[i][j >> 1]);
            float v = ((j & 1) ? pr.y : pr.x) + bias[j];
            int col = col0 + j;
            if (mode == 0) {
                int g  = col >> 9;
                int mc = col & 511;
                g_iouT[(((size_t)t * 4 + g) * 512 + mc) * 64 + b] = v;
            } else if (mode == 1) {
                g_ctxT[(size_t)t * (512 * 64) + (size_t)col * 64 + b] = v;
            } else {
                g_wcsT[(size_t)t * (512 * 64) + (size_t)col * 64 + b] = tanhf(v);
            }
        }
    }
}

// ---------------------------------------------------------------------------
// Persistent weight-stationary scan with FFMA2. 128 blocks, 256 threads.
// Weights duplicated as (w,w) pairs in dynamic smem (~80KB), kc-skewed.
// warp = m_local(4) x bhalf(2); lane = kc(bits3-4) x bq(bits0-2).
// ---------------------------------------------------------------------------
#define W4TOT 16448                       /* floats: 4 m * (4 kc * 1028) */
#define SCAN_SMEM_FLOATS (W4TOT + 4 * 1032)
#define SCAN_SMEM_BYTES  (SCAN_SMEM_FLOATS * 4)

__global__ void __launch_bounds__(256) scan_kernel(
    const float* __restrict__ W_iouh, const float* __restrict__ b_iouh,
    const float* __restrict__ W_fh,   const float* __restrict__ b_fh,
    const float* __restrict__ c0)
{
    extern __shared__ float sm[];

    const int tid   = threadIdx.x;
    const int warp  = tid >> 5;
    const int lane  = tid & 31;
    const int m_l   = warp >> 1;
    const int bhalf = warp & 1;
    const int kc    = (lane >> 3) & 3;
    const int bq    = lane & 7;
    const int m     = blockIdx.x * 4 + m_l;
    const int b_own = bhalf * 32 + bq * 4 + kc;

    // ---- weights into smem, duplicated (w,w) pairs ----
    // gate weights: sm[ml*4112 + kc*1028 + i*8 + g*2 + {0,1}]
    for (int idx = tid; idx < 8192; idx += 256) {
        int ml = idx >> 11;
        int r  = idx & 2047;
        int c  = r >> 9;
        int r2 = r & 511;
        int i  = r2 >> 2;
        int g  = r2 & 3;
        int mg = blockIdx.x * 4 + ml;
        float w = W_iouh[((size_t)g * 512 + mg) * 512 + c * 128 + i];
        float* p = sm + ml * 4112 + c * 1028 + i * 8 + g * 2;
        p[0] = w; p[1] = w;
    }
    // W_fh: sm[W4TOT + ml*1032 + kc*258 + i*2 + {0,1}]
    for (int idx = tid; idx < 2048; idx += 256) {
        int ml = idx >> 9;
        int r  = idx & 511;
        int c  = r >> 7;
        int i  = r & 127;
        int mg = blockIdx.x * 4 + ml;
        float w = W_fh[(size_t)mg * 512 + c * 128 + i];
        float* p = sm + W4TOT + ml * 1032 + c * 258 + i * 2;
        p[0] = w; p[1] = w;
    }
    __syncthreads();

    const float bf  = b_iouh[m];
    const float bi  = b_iouh[512 + m];
    const float bo  = b_iouh[1024 + m];
    const float boc = b_iouh[1536 + m];
    const float bfh = b_fh[m];

    float c_reg = c0[(size_t)b_own * 512 + m];

    const float4* w4f = reinterpret_cast<const float4*>(sm + m_l * 4112 + kc * 1028);
    const float2* w1f = reinterpret_cast<const float2*>(sm + W4TOT + m_l * 1032 + kc * 258);
    const int hoff = kc * 2048 + bhalf * 8 + bq;   // float4 index within step slice

    for (int t = 0; t < SEQ_T; t++) {
        const float* hb = (t == 0) ? g_h0T : (g_hT + (size_t)(t - 1) * (DIM * NB));
        const float4* hp = reinterpret_cast<const float4*>(hb) + hoff;

        // hoisted addend loads (L2 latency hidden under the inner loop)
        const size_t ib = (((size_t)t * 4) * 512 + m) * 64 + b_own;
        const size_t sb = (size_t)t * (512 * 64) + (size_t)m * 64 + b_own;
        float af  = __ldg(&g_iouT[ib]);
        float ai  = __ldg(&g_iouT[ib + 1 * 512 * 64]);
        float ao  = __ldg(&g_iouT[ib + 2 * 512 * 64]);
        float aoc = __ldg(&g_iouT[ib + 3 * 512 * 64]);
        float act = __ldg(&g_ctxT[sb]);
        float aw  = __ldg(&g_wcsT[sb]);

        ull acc2[2][5];
        #pragma unroll
        for (int p = 0; p < 2; p++)
            #pragma unroll
            for (int g = 0; g < 5; g++) acc2[p][g] = 0ull;

        #pragma unroll 8
        for (int i = 0; i < 128; i++) {
            float4 h4 = __ldg(hp + i * 16);
            ulonglong2 hv = *reinterpret_cast<ulonglong2*>(&h4);
            float4 wa = w4f[i * 2];
            float4 wb = w4f[i * 2 + 1];
            float2 wc = w1f[i];
            ull w0 = reinterpret_cast<ulonglong2*>(&wa)->x;   // (g0,g0)
            ull w1 = reinterpret_cast<ulonglong2*>(&wa)->y;   // (g1,g1)
            ull w2 = reinterpret_cast<ulonglong2*>(&wb)->x;   // (g2,g2)
            ull w3 = reinterpret_cast<ulonglong2*>(&wb)->y;   // (g3,g3)
            ull w4 = *reinterpret_cast<ull*>(&wc);            // (w1,w1)
            ffma2(acc2[0][0], hv.x, w0);
            ffma2(acc2[0][1], hv.x, w1);
            ffma2(acc2[0][2], hv.x, w2);
            ffma2(acc2[0][3], hv.x, w3);
            ffma2(acc2[0][4], hv.x, w4);
            ffma2(acc2[1][0], hv.y, w0);
            ffma2(acc2[1][1], hv.y, w1);
            ffma2(acc2[1][2], hv.y, w2);
            ffma2(acc2[1][3], hv.y, w3);
            ffma2(acc2[1][4], hv.y, w4);
        }

        // unpack: a[j*5+g], j = 2*p + half
        float a[20];
        #pragma unroll
        for (int p = 0; p < 2; p++)
            #pragma unroll
            for (int g = 0; g < 5; g++) {
                float2 v = *reinterpret_cast<float2*>(&acc2[p][g]);
                a[(2 * p + 0) * 5 + g] = v.x;
                a[(2 * p + 1) * 5 + g] = v.y;
            }

        #pragma unroll
        for (int q = 0; q < 20; q++) {
            a[q] += __shfl_xor_sync(0xffffffffu, a[q], 8);
            a[q] += __shfl_xor_sync(0xffffffffu, a[q], 16);
        }

        float fg  = sigmoid_fast(a[kc * 5 + 0] + af  + bf);
        float ig  = sigmoid_fast(a[kc * 5 + 1] + ai  + bi);
        float og  = sigmoid_fast(a[kc * 5 + 2] + ao  + bo);
        float ocg = sigmoid_fast(a[kc * 5 + 3] + aoc + boc);
        float ct  = tanh_fast   (a[kc * 5 + 4] + act + bfh);

        c_reg = ig * ct + fg * c_reg;
        float hv = og * tanh_fast(c_reg) + ocg * aw;

        g_hT[sb] = hv;

        // ---- grid barrier: bar.sync, then elected thread release+arrive+spin
        __syncthreads();
        if (tid == 0) {
            __threadfence();
            atomicAdd(&g_cnt, 1u);
            const unsigned target = (unsigned)gridDim.x * (unsigned)(t + 1);
            while (*reinterpret_cast<volatile unsigned*>(&g_cnt) < target) { }
            __threadfence();
        }
        __syncthreads();
    }

    g_cT[(size_t)m * 64 + b_own] = c_reg;
}

// ---------------------------------------------------------------------------
// transpose g_hT [t][m][b] -> out [t][b][m]
// ---------------------------------------------------------------------------
__global__ void __launch_bounds__(256) transpose_kernel(float* __restrict__ out)
{
    __shared__ float tile[32][33];
    const int tx = threadIdx.x;       // 0..31
    const int ty = threadIdx.y;       // 0..7
    const int m0 = blockIdx.x * 32;
    const int b0 = blockIdx.y * 32;
    const int t  = blockIdx.z;

    const float* src = g_hT + (size_t)t * (512 * 64);
    #pragma unroll
    for (int k = 0; k < 4; k++)
        tile[ty + 8 * k][tx] = src[(size_t)(m0 + ty + 8 * k) * 64 + b0 + tx];
    __syncthreads();
    float* dst = out + (size_t)t * (64 * 512);
    #pragma unroll
    for (int k = 0; k < 4; k++)
        dst[(size_t)(b0 + ty + 8 * k) * 512 + m0 + tx] = tile[tx][ty + 8 * k];
}

__global__ void tail_kernel(float* __restrict__ out)
{
    int b = blockIdx.x;      // 64
    int m = threadIdx.x;     // 512
    out[TBM + (size_t)b * 512 + m]             = g_cT[(size_t)m * 64 + b];
    out[TBM + NB * DIM + (size_t)b * 512 + m]  = g_hT[(size_t)255 * (512 * 64) + (size_t)m * 64 + b];
}

// ---------------------------------------------------------------------------
extern "C" void kernel_launch(void* const* d_in, const int* in_sizes, int n_in,
                              void* d_out, int out_size)
{
    const float* inputs = (const float*)d_in[0];
    const float* emb_s  = (const float*)d_in[1];
    const float* c0     = (const float*)d_in[2];
    const float* h0     = (const float*)d_in[3];
    const float* W_ioux = (const float*)d_in[4];
    const float* b_ioux = (const float*)d_in[5];
    const float* W_iouh = (const float*)d_in[6];
    const float* b_iouh = (const float*)d_in[7];
    const float* W_ious = (const float*)d_in[8];
    const float* b_ious = (const float*)d_in[9];
    const float* W_fx   = (const float*)d_in[10];
    const float* b_fx   = (const float*)d_in[11];
    const float* W_fh   = (const float*)d_in[12];
    const float* b_fh   = (const float*)d_in[13];
    const float* W_wc   = (const float*)d_in[14];
    const float* b_wc   = (const float*)d_in[15];
    float* out = (float*)d_out;

    static int smem_set = 0;
    if (!smem_set) {
        cudaFuncSetAttribute(scan_kernel, cudaFuncAttributeMaxDynamicSharedMemorySize,
                             SCAN_SMEM_BYTES);
        smem_set = 1;
    }

    init_kernel<<<64, 512>>>(h0);
    gemm_kernel<<<dim3(16, 128), 256>>>(0, inputs, emb_s, W_ioux, W_ious,
                                        b_ioux, b_ious, 2048, 1024);
    gemm_kernel<<<dim3(4, 128), 256>>>(1, inputs, nullptr, W_fx, nullptr,
                                       b_fx, nullptr, 512, 512);
    gemm_kernel<<<dim3(4, 128), 256>>>(2, emb_s, nullptr, W_wc, nullptr,
                                       b_wc, nullptr, 512, 512);
    scan_kernel<<<128, 256, SCAN_SMEM_BYTES>>>(W_iouh, b_iouh, W_fh, b_fh, c0);
    transpose_kernel<<<dim3(16, 2, 256), dim3(32, 8)>>>(out);
    tail_kernel<<<64, 512>>>(out);
}